// round 6
// baseline (speedup 1.0000x reference)
#include <cuda_runtime.h>

#define NN 50000
#define EE 800000
#define ET (EE + NN)

// ---------------- scratch (device globals; no allocations allowed) ----------
__device__ float g_xl[NN * 128];     // per-layer transformed features [N, M]
__device__ float g_h[NN * 128];      // layer activations (inter-layer buffer)
__device__ float g_out[NN * 128];    // aggregation accumulator [N, M]
__device__ float g_s[NN * 2];        // alpha_src per (node, head)
__device__ float g_d[NN * 2];        // alpha_dst per (node, head)
__device__ int   g_emax[NN * 2];     // segment max (order-encoded float)
__device__ float g_denom[NN * 2];    // softmax denominators
__device__ float g_ebuf[(size_t)ET * 2];  // per-edge e / exp values

// order-preserving float<->int encoding for atomicMax on signed int
__device__ __forceinline__ int enc_f(float f) {
    int b = __float_as_int(f);
    return b >= 0 ? b : (b ^ 0x7FFFFFFF);
}
__device__ __forceinline__ float dec_f(int e) {
    return __int_as_float(e >= 0 ? e : (e ^ 0x7FFFFFFF));
}

// ---------------- GEMM: [N,128] @ [128,BN] -> g_xl[N,BN] --------------------
// src_is_gh != 0 -> read input activations from g_h instead of A.
template <int BN>
__global__ void gemm_kernel(const float* __restrict__ A,
                            const float* __restrict__ B, int src_is_gh) {
    constexpr int BM = 64, BK = 32, TM = 4, TN = BN / 16;
    __shared__ float As[BM][BK + 1];
    __shared__ float Bs[BK][BN];
    const float* __restrict__ Ab = src_is_gh ? (const float*)g_h : A;
    const int tid = threadIdx.x;
    const int tx = tid & 15, ty = tid >> 4;
    const int row0 = blockIdx.x * BM;

    float acc[TM][TN];
#pragma unroll
    for (int i = 0; i < TM; i++)
#pragma unroll
        for (int j = 0; j < TN; j++) acc[i][j] = 0.f;

    for (int k0 = 0; k0 < 128; k0 += BK) {
#pragma unroll
        for (int l = 0; l < (BM * BK) / 256; l++) {
            int idx = l * 256 + tid;
            int r = idx >> 5, c = idx & 31;
            int gr = row0 + r;
            As[r][c] = (gr < NN) ? Ab[(size_t)gr * 128 + k0 + c] : 0.f;
        }
#pragma unroll
        for (int l = 0; l < (BK * BN) / 256; l++) {
            int idx = l * 256 + tid;
            int r = idx / BN, c = idx % BN;
            Bs[r][c] = B[(size_t)(k0 + r) * BN + c];
        }
        __syncthreads();
#pragma unroll
        for (int k = 0; k < BK; k++) {
            float a[TM], bb[TN];
#pragma unroll
            for (int i = 0; i < TM; i++) a[i] = As[ty * TM + i][k];
#pragma unroll
            for (int j = 0; j < TN; j++) bb[j] = Bs[k][tx * TN + j];
#pragma unroll
            for (int i = 0; i < TM; i++)
#pragma unroll
                for (int j = 0; j < TN; j++) acc[i][j] += a[i] * bb[j];
        }
        __syncthreads();
    }
#pragma unroll
    for (int i = 0; i < TM; i++) {
        int gr = row0 + ty * TM + i;
        if (gr < NN) {
#pragma unroll
            for (int j = 0; j < TN; j++)
                g_xl[(size_t)gr * BN + tx * TN + j] = acc[i][j];
        }
    }
}

// ---------------- per-(node,head) attention dot products --------------------
__global__ void att_kernel(const float* __restrict__ asrc,
                           const float* __restrict__ adst, int Hh) {
    int g = (blockIdx.x * blockDim.x + threadIdx.x) >> 5;
    int lane = threadIdx.x & 31;
    if (g >= NN * Hh) return;
    int node = g / Hh;
    int h = g - node * Hh;
    const float* row = g_xl + (size_t)node * Hh * 64 + h * 64;
    float v0 = row[lane], v1 = row[lane + 32];
    float vs = v0 * asrc[h * 64 + lane] + v1 * asrc[h * 64 + lane + 32];
    float vd = v0 * adst[h * 64 + lane] + v1 * adst[h * 64 + lane + 32];
#pragma unroll
    for (int o = 16; o; o >>= 1) {
        vs += __shfl_down_sync(0xFFFFFFFFu, vs, o);
        vd += __shfl_down_sync(0xFFFFFFFFu, vd, o);
    }
    if (lane == 0) {
        g_s[node * Hh + h] = vs;
        g_d[node * Hh + h] = vd;
    }
}

// ---------------- init accumulators -----------------------------------------
__global__ void init_kernel(int M) {
    int i = blockIdx.x * blockDim.x + threadIdx.x;
    if (i < NN * M) g_out[i] = 0.f;
    if (i < NN * 2) {
        g_emax[i] = (int)0x80000000;
        g_denom[i] = 0.f;
    }
}

// ---------------- edge pass 1: e = lrelu(s[src]+d[dst]); segment max --------
__global__ void edge_max_kernel(const int* __restrict__ ei, int Hh) {
    int e = blockIdx.x * blockDim.x + threadIdx.x;
    if (e >= ET) return;
    int s, d;
    if (e < EE) { s = ei[e]; d = ei[EE + e]; }
    else        { s = d = e - EE; }
#pragma unroll 2
    for (int h = 0; h < Hh; h++) {
        float v = g_s[s * Hh + h] + g_d[d * Hh + h];
        v = v > 0.f ? v : 0.2f * v;
        g_ebuf[(size_t)e * Hh + h] = v;
        atomicMax(&g_emax[d * Hh + h], enc_f(v));
    }
}

// ---------------- edge pass 2: exp + denom ----------------------------------
__global__ void edge_exp_kernel(const int* __restrict__ ei, int Hh) {
    int e = blockIdx.x * blockDim.x + threadIdx.x;
    if (e >= ET) return;
    int d;
    if (e < EE) d = ei[EE + e];
    else        d = e - EE;
#pragma unroll 2
    for (int h = 0; h < Hh; h++) {
        float m = dec_f(g_emax[d * Hh + h]);
        float ex = __expf(g_ebuf[(size_t)e * Hh + h] - m);
        g_ebuf[(size_t)e * Hh + h] = ex;
        atomicAdd(&g_denom[d * Hh + h], ex);
    }
}

// ---------------- edge pass 3: message scatter (one warp per edge) ----------
__global__ void scatter_kernel(const int* __restrict__ ei, int Hh) {
    int g = (blockIdx.x * blockDim.x + threadIdx.x) >> 5;
    int lane = threadIdx.x & 31;
    if (g >= ET) return;
    int s, d;
    if (g < EE) { s = ei[g]; d = ei[EE + g]; }
    else        { s = d = g - EE; }
    const int M = Hh * 64;
    float a0 = g_ebuf[(size_t)g * Hh] / g_denom[d * Hh];
    float a1 = (Hh == 2) ? g_ebuf[(size_t)g * Hh + 1] / g_denom[d * Hh + 1] : 0.f;
    const float* xr = g_xl + (size_t)s * M;
    float* orow = g_out + (size_t)d * M;
#pragma unroll
    for (int i = lane; i < 128; i += 32) {
        if (i < M) {
            float a = (i < 64) ? a0 : a1;
            atomicAdd(&orow[i], xr[i] * a);
        }
    }
}

// ---------------- finalize: bias (+ elu); dst selected by flag --------------
__global__ void finalize_kernel(const float* __restrict__ bias,
                                float* __restrict__ outp, int M, int do_elu,
                                int dst_is_gh) {
    int i = blockIdx.x * blockDim.x + threadIdx.x;
    if (i >= NN * M) return;
    float v = g_out[i] + bias[i % M];
    if (do_elu) v = v > 0.f ? v : expm1f(v);
    if (dst_is_gh) g_h[i] = v;
    else           outp[i] = v;
}

// ---------------- host-side layer driver (kernel launches ONLY) -------------
static void run_layer(const float* in, const float* W, const float* asrc,
                      const float* adst, const float* bias, float* outp,
                      int Hh, const int* ei, int do_elu,
                      int src_is_gh, int dst_is_gh) {
    const int M = Hh * 64;
    if (M == 128)
        gemm_kernel<128><<<(NN + 63) / 64, 256>>>(in, W, src_is_gh);
    else
        gemm_kernel<64><<<(NN + 63) / 64, 256>>>(in, W, src_is_gh);

    int warps = NN * Hh;
    att_kernel<<<(warps * 32 + 255) / 256, 256>>>(asrc, adst, Hh);

    init_kernel<<<(NN * M + 255) / 256, 256>>>(M);
    edge_max_kernel<<<(ET + 255) / 256, 256>>>(ei, Hh);
    edge_exp_kernel<<<(ET + 255) / 256, 256>>>(ei, Hh);
    scatter_kernel<<<(ET * 32 + 255) / 256, 256>>>(ei, Hh);
    finalize_kernel<<<(NN * M + 255) / 256, 256>>>(bias, outp, M, do_elu,
                                                   dst_is_gh);
}

extern "C" void kernel_launch(void* const* d_in, const int* in_sizes, int n_in,
                              void* d_out, int out_size) {
    const float* x   = (const float*)d_in[0];
    const int*   ei  = (const int*)d_in[1];   // int64 in reference -> int32 in harness
    const float* W0  = (const float*)d_in[2];
    const float* as0 = (const float*)d_in[3];
    const float* ad0 = (const float*)d_in[4];
    const float* b0  = (const float*)d_in[5];
    const float* W1  = (const float*)d_in[6];
    const float* as1 = (const float*)d_in[7];
    const float* ad1 = (const float*)d_in[8];
    const float* b1  = (const float*)d_in[9];
    const float* W2  = (const float*)d_in[10];
    const float* as2 = (const float*)d_in[11];
    const float* ad2 = (const float*)d_in[12];
    const float* b2  = (const float*)d_in[13];

    // layer 0: input x (external), output -> g_h
    run_layer(x, W0, as0, ad0, b0, nullptr, 2, ei, 1, /*src_gh=*/0, /*dst_gh=*/1);
    // layer 1: input g_h, output -> g_h
    run_layer(x, W1, as1, ad1, b1, nullptr, 2, ei, 1, /*src_gh=*/1, /*dst_gh=*/1);
    // layer 2: input g_h, output -> d_out
    run_layer(x, W2, as2, ad2, b2, (float*)d_out, 1, ei, 0, /*src_gh=*/1, /*dst_gh=*/0);
}